// round 16
// baseline (speedup 1.0000x reference)
#include <cuda_runtime.h>
#include <cuda_fp16.h>
#include <math.h>
#include <stdint.h>

// ---------------------------------------------------------------------------
// MoE FFN + residual + LayerNorm. fp16 mma.sync GEMMs, 128x64 tile, 3 CTAs/SM.
// T=8192 tokens, D=1024, H=2048, E=8 experts, top-2.
// ---------------------------------------------------------------------------

constexpr int T_TOK = 8192;
constexpr int D_IN  = 1024;
constexpr int D_HID = 2048;
constexpr int NEXP  = 8;

constexpr int BM = 128;
constexpr int MAX_ROWS  = T_TOK * 2 + NEXP * BM; // 17408
constexpr int MAX_TILES = MAX_ROWS / BM;         // 136

// ------------------------- device scratch (static) -------------------------
__device__ __half g_hh [(size_t)MAX_ROWS * D_HID];       // GEMM1 out (fp16)
__device__ __half g_yh [(size_t)MAX_ROWS * D_IN];        // GEMM2 out (fp16)
__device__ __half g_xh [(size_t)T_TOK * D_IN];           // x  -> fp16 (in gate)
__device__ __half g_w1h[(size_t)NEXP * D_IN * D_HID];    // W1 -> fp16
__device__ __half g_w2h[(size_t)NEXP * D_HID * D_IN];    // W2 -> fp16
__device__ int   g_row_token[MAX_ROWS];
__device__ int   g_pos_of[T_TOK * 2];
__device__ int   g_sel[T_TOK * 2];
__device__ float g_gate[T_TOK * 2];
__device__ int   g_tile_expert[MAX_TILES];
__device__ int   g_n_tiles;

// --------------------------- PTX helpers -----------------------------------
__device__ __forceinline__ uint32_t smem_u32(const void* p) {
    uint32_t a;
    asm("{ .reg .u64 t; cvta.to.shared.u64 t, %1; cvt.u32.u64 %0, t; }"
        : "=r"(a) : "l"(p));
    return a;
}
__device__ __forceinline__ void mma_16816(float* c, const uint32_t* a,
                                          const uint32_t* b) {
    asm volatile(
        "mma.sync.aligned.m16n8k16.row.col.f32.f16.f16.f32 "
        "{%0,%1,%2,%3}, {%4,%5,%6,%7}, {%8,%9}, {%0,%1,%2,%3};"
        : "+f"(c[0]), "+f"(c[1]), "+f"(c[2]), "+f"(c[3])
        : "r"(a[0]), "r"(a[1]), "r"(a[2]), "r"(a[3]), "r"(b[0]), "r"(b[1]));
}
__device__ __forceinline__ void ldm_x4(uint32_t* r, uint32_t addr) {
    asm volatile("ldmatrix.sync.aligned.m8n8.x4.shared.b16 {%0,%1,%2,%3}, [%4];"
                 : "=r"(r[0]), "=r"(r[1]), "=r"(r[2]), "=r"(r[3]) : "r"(addr));
}
__device__ __forceinline__ void ldm_x4_t(uint32_t* r, uint32_t addr) {
    asm volatile("ldmatrix.sync.aligned.m8n8.x4.trans.shared.b16 {%0,%1,%2,%3}, [%4];"
                 : "=r"(r[0]), "=r"(r[1]), "=r"(r[2]), "=r"(r[3]) : "r"(addr));
}
__device__ __forceinline__ void cp16(uint32_t dst, const void* src, uint32_t sz) {
    asm volatile("cp.async.cg.shared.global [%0], [%1], 16, %2;"
                 :: "r"(dst), "l"(src), "r"(sz));
}
#define CP_COMMIT() asm volatile("cp.async.commit_group;" ::: "memory")
template <int N>
__device__ __forceinline__ void cp_wait() {
    asm volatile("cp.async.wait_group %0;" :: "n"(N) : "memory");
}

// ---------------- fused fp32 -> fp16 convert for W1 + W2 (proven) -----------
__global__ void k_cvt_w(const float4* __restrict__ w1, uint4* __restrict__ w1h,
                        const float4* __restrict__ w2, uint4* __restrict__ w2h,
                        int n8) {
    int i = blockIdx.x * blockDim.x + threadIdx.x;
    const float4* src; uint4* dst; int j;
    if (i < n8) { src = w1; dst = w1h; j = i; }
    else if (i < 2 * n8) { src = w2; dst = w2h; j = i - n8; }
    else return;
    float4 v0 = src[(size_t)j * 2], v1 = src[(size_t)j * 2 + 1];
    __half2 h0 = __floats2half2_rn(v0.x, v0.y);
    __half2 h1 = __floats2half2_rn(v0.z, v0.w);
    __half2 h2 = __floats2half2_rn(v1.x, v1.y);
    __half2 h3 = __floats2half2_rn(v1.z, v1.w);
    uint4 o;
    o.x = *reinterpret_cast<uint32_t*>(&h0);
    o.y = *reinterpret_cast<uint32_t*>(&h1);
    o.z = *reinterpret_cast<uint32_t*>(&h2);
    o.w = *reinterpret_cast<uint32_t*>(&h3);
    dst[j] = o;
}

// ----- gating (fp32, exact) + x->fp16 + row_token init (no atomics) ---------
__global__ void k_gate(const float* __restrict__ x, const float* __restrict__ Wg,
                       __half* __restrict__ xh) {
    int gid = blockIdx.x * blockDim.x + threadIdx.x;
    if (gid < MAX_ROWS) g_row_token[gid] = -1;

    int warp = threadIdx.x >> 5;
    int lane = threadIdx.x & 31;
    int t = blockIdx.x * 8 + warp;
    if (t >= T_TOK) return;
    const float* xr = x + (size_t)t * D_IN;
    __half* xhr = xh + (size_t)t * D_IN;
    const float4* wg4 = reinterpret_cast<const float4*>(Wg);

    float acc[8];
#pragma unroll
    for (int j = 0; j < 8; j++) acc[j] = 0.f;
    for (int i = lane; i < D_IN; i += 32) {
        float xv = xr[i];
        xhr[i] = __float2half_rn(xv);
        float4 a = wg4[i * 2];
        float4 b = wg4[i * 2 + 1];
        acc[0] += xv * a.x; acc[1] += xv * a.y; acc[2] += xv * a.z; acc[3] += xv * a.w;
        acc[4] += xv * b.x; acc[5] += xv * b.y; acc[6] += xv * b.z; acc[7] += xv * b.w;
    }
#pragma unroll
    for (int j = 0; j < 8; j++) {
#pragma unroll
        for (int off = 16; off; off >>= 1)
            acc[j] += __shfl_down_sync(0xffffffff, acc[j], off);
    }
    if (lane == 0) {
        int i0 = 0; float v0 = acc[0];
#pragma unroll
        for (int e = 1; e < 8; e++) if (acc[e] > v0) { v0 = acc[e]; i0 = e; }
        int i1 = -1; float v1 = -3.4e38f;
#pragma unroll
        for (int e = 0; e < 8; e++)
            if (e != i0 && acc[e] > v1) { v1 = acc[e]; i1 = e; }
        float e1 = expf(v1 - v0);
        float inv = 1.f / (1.f + e1);
        g_sel[2 * t] = i0;  g_sel[2 * t + 1] = i1;
        g_gate[2 * t] = inv; g_gate[2 * t + 1] = e1 * inv;
    }
}

// ------ loss reduction + scan (tid 0) + scatter (phase 2), single block -----
__global__ void k_scan_scatter_loss(float* __restrict__ loss_out) {
    __shared__ float simp[NEXP * 256];
    __shared__ float sld[NEXP * 256];
    __shared__ float rimp[NEXP], rld[NEXP];
    __shared__ int   s_cursor[NEXP];
    int tid = threadIdx.x;

    float imp[NEXP], ld[NEXP];
#pragma unroll
    for (int e = 0; e < NEXP; e++) { imp[e] = 0.f; ld[e] = 0.f; }
    for (int t = tid; t < T_TOK; t += 256) {
#pragma unroll
        for (int slot = 0; slot < 2; slot++) {
            int e = g_sel[2 * t + slot];
            imp[e] += g_gate[2 * t + slot];
            ld[e]  += 1.f;
        }
    }
#pragma unroll
    for (int e = 0; e < NEXP; e++) {
        simp[e * 256 + tid] = imp[e];
        sld[e * 256 + tid]  = ld[e];
    }
    __syncthreads();
    if (tid < NEXP) {
        float si = 0.f, sl = 0.f;
        for (int j = 0; j < 256; j++) { si += simp[tid * 256 + j]; sl += sld[tid * 256 + j]; }
        rimp[tid] = si; rld[tid] = sl;
    }
    __syncthreads();
    if (tid == 0) {
        int total_tiles = 0, pos = 0;
        for (int e = 0; e < NEXP; e++) {
            s_cursor[e] = pos;
            int cnt = (int)rld[e];
            int nt = (cnt + BM - 1) / BM;
            for (int j = 0; j < nt; j++) g_tile_expert[total_tiles + j] = e;
            total_tiles += nt;
            pos += nt * BM;
        }
        g_n_tiles = total_tiles;

        float mi = 0.f, ml = 0.f;
        for (int e = 0; e < NEXP; e++) { mi += rimp[e]; ml += rld[e]; }
        mi *= (1.f / NEXP); ml *= (1.f / NEXP);
        float vi = 0.f, vl = 0.f;
        for (int e = 0; e < NEXP; e++) {
            float d1 = rimp[e] - mi; vi += d1 * d1;
            float d2 = rld[e]  - ml; vl += d2 * d2;
        }
        vi *= (1.f / NEXP); vl *= (1.f / NEXP);
        *loss_out = vi / (mi * mi + 1e-10f) + vl / (ml * ml + 1e-10f);
    }
    __syncthreads();

    for (int t = tid; t < T_TOK; t += 256) {
#pragma unroll
        for (int slot = 0; slot < 2; slot++) {
            int e = g_sel[2 * t + slot];
            int p = atomicAdd(&s_cursor[e], 1);
            g_row_token[p] = t;
            g_pos_of[2 * t + slot] = p;
        }
    }
}

// ------------------------- fp16 mma GEMM, 128x64 tile -----------------------
// C[128 x 64] = A[128 x K] @ B[K x 64] (+bias, opt relu). BK=32, 2-stage,
// 8 warps x (32x32) microtile, 3 CTAs/SM.
// As: [128][40] halfs (80B rows, ldmatrix conflict-free)
// Bs: [32][72]  halfs (144B rows, bank step 4 -> ldmatrix.trans conflict-free)
constexpr int AS_HSTRIDE = 40;
constexpr int BS_HSTRIDE = 72;
constexpr int AS_BYTES = 128 * AS_HSTRIDE * 2;        // 10240
constexpr int BS_BYTES = 32 * BS_HSTRIDE * 2;         // 4608
constexpr int OFF_AS0 = 0;
constexpr int OFF_AS1 = AS_BYTES;
constexpr int OFF_BS0 = 2 * AS_BYTES;                 // 20480
constexpr int OFF_BS1 = 2 * AS_BYTES + BS_BYTES;      // 25088
constexpr int OFF_BIAS = 2 * AS_BYTES + 2 * BS_BYTES; // 29696
constexpr int SMEM_BYTES = OFF_BIAS + 256;            // 29952

template <int NTOT, int K, bool GATHER, bool RELU>
__global__ void __launch_bounds__(256, 3) k_gemm_h(const __half* __restrict__ A,
                                                   const __half* __restrict__ Bg,
                                                   const float* __restrict__ bias,
                                                   __half* __restrict__ C) {
    extern __shared__ char smem[];
    uint32_t sb = smem_u32(smem);
    int tile = blockIdx.x;
    if (tile >= g_n_tiles) return;
    int e    = g_tile_expert[tile];
    int row0 = tile * BM;
    int n0   = blockIdx.y * 64;
    int tid  = threadIdx.x;
    int lane = tid & 31, wid = tid >> 5;
    int g = lane >> 2, t = lane & 3;
    int m_off = (wid & 3) * 32;
    int n_off = (wid >> 2) * 32;

    float* sbias = (float*)(smem + OFF_BIAS);
    if (tid < 64) sbias[tid] = bias[(size_t)e * NTOT + n0 + tid];

    // ---- cp.async mapping ----
    // A: 128 rows x 64B -> 2 thr/row, 2 cp16 each (same as R6)
    int arow = tid >> 1;
    const __half* asrc; uint32_t avalid = 16u;
    if (GATHER) {
        int tok = g_row_token[row0 + arow];
        avalid = (tok >= 0) ? 16u : 0u;
        asrc = A + (size_t)(tok < 0 ? 0 : tok) * K;
    } else {
        asrc = A + (size_t)(row0 + arow) * K;
    }
    int au = (tid & 1) * 2;
    // B: 32 rows x 128B -> 8 thr/row, 1 cp16 each
    int brow = tid >> 3;
    int bu = tid & 7;
    const __half* bsrc = Bg + (size_t)e * K * NTOT + (size_t)brow * NTOT + n0 + bu * 8;

    uint32_t a_dst0 = sb + OFF_AS0 + arow * (AS_HSTRIDE * 2) + au * 16;
    uint32_t a_dst1 = sb + OFF_AS1 + arow * (AS_HSTRIDE * 2) + au * 16;
    uint32_t b_dst0 = sb + OFF_BS0 + brow * (BS_HSTRIDE * 2) + bu * 16;
    uint32_t b_dst1 = sb + OFF_BS1 + brow * (BS_HSTRIDE * 2) + bu * 16;

    auto load_chunk = [&](int i, int s) {
        int k0 = i * 32;
        uint32_t ad = s ? a_dst1 : a_dst0;
        uint32_t bd = s ? b_dst1 : b_dst0;
        const __half* ap = asrc + k0 + au * 8;
        const __half* bp = bsrc + (size_t)k0 * NTOT;
#pragma unroll
        for (int j = 0; j < 2; j++) cp16(ad + j * 16, ap + j * 8, avalid);
        cp16(bd, bp, 16u);
        CP_COMMIT();
    };

    // ---- ldmatrix per-lane base offsets ----
    uint32_t a_lm = (uint32_t)((m_off + (lane & 7) + ((lane >> 3) & 1) * 8) * (AS_HSTRIDE * 2)
                               + (lane >> 4) * 16);
    uint32_t b_lm = (uint32_t)(((lane & 7) + ((lane >> 3) & 1) * 8) * (BS_HSTRIDE * 2)
                               + (n_off + (lane >> 4) * 8) * 2);

    float acc[2][4][4];
#pragma unroll
    for (int mt = 0; mt < 2; mt++)
#pragma unroll
        for (int nt = 0; nt < 4; nt++)
#pragma unroll
            for (int q = 0; q < 4; q++) acc[mt][nt][q] = 0.f;

    load_chunk(0, 0);
    load_chunk(1, 1);

    constexpr int NK = K / 32;
    for (int i = 0; i < NK; i++) {
        int s = i & 1;
        if (i + 1 < NK) cp_wait<1>(); else cp_wait<0>();
        __syncthreads();
        uint32_t as_base = sb + (s ? OFF_AS1 : OFF_AS0) + a_lm;
        uint32_t bs_base = sb + (s ? OFF_BS1 : OFF_BS0) + b_lm;
#pragma unroll
        for (int ks = 0; ks < 2; ks++) {
            uint32_t a[2][4], b[4][2];
#pragma unroll
            for (int mt = 0; mt < 2; mt++)
                ldm_x4(a[mt], as_base + ks * 32 + mt * 16 * (AS_HSTRIDE * 2));
#pragma unroll
            for (int p = 0; p < 2; p++) {
                uint32_t r[4];
                ldm_x4_t(r, bs_base + ks * 16 * (BS_HSTRIDE * 2) + p * 32);
                b[2 * p][0] = r[0]; b[2 * p][1] = r[1];
                b[2 * p + 1][0] = r[2]; b[2 * p + 1][1] = r[3];
            }
#pragma unroll
            for (int mt = 0; mt < 2; mt++)
#pragma unroll
                for (int nt = 0; nt < 4; nt++)
                    mma_16816(acc[mt][nt], a[mt], b[nt]);
        }
        __syncthreads();
        if (i + 2 < NK) load_chunk(i + 2, s);
    }

    // ---- epilogue (fp16 out) ----
#pragma unroll
    for (int mt = 0; mt < 2; mt++) {
        int r0 = row0 + m_off + mt * 16 + g;
        __half* c0 = C + (size_t)r0 * NTOT + n0;
        __half* c1 = c0 + (size_t)8 * NTOT;
#pragma unroll
        for (int nt = 0; nt < 4; nt++) {
            int col = n_off + nt * 8 + t * 2;
            float v[4];
            v[0] = acc[mt][nt][0] + sbias[col];
            v[1] = acc[mt][nt][1] + sbias[col + 1];
            v[2] = acc[mt][nt][2] + sbias[col];
            v[3] = acc[mt][nt][3] + sbias[col + 1];
            if (RELU) {
#pragma unroll
                for (int q = 0; q < 4; q++) v[q] = fmaxf(v[q], 0.f);
            }
            *reinterpret_cast<__half2*>(c0 + col) = __floats2half2_rn(v[0], v[1]);
            *reinterpret_cast<__half2*>(c1 + col) = __floats2half2_rn(v[2], v[3]);
        }
    }
}

// ----------- combine + residual + LayerNorm (vectorized, 1-pass stats) ------
__global__ void __launch_bounds__(256) k_combine(const float* __restrict__ x,
                                                 const float* __restrict__ gamma,
                                                 const float* __restrict__ beta,
                                                 float* __restrict__ out) {
    __shared__ float vals[D_IN];
    __shared__ float wsum[8], wsq[8];
    __shared__ float s_mu, s_rs;
    int t = blockIdx.x;
    int tid = threadIdx.x;
    int lane = tid & 31, wid = tid >> 5;

    int   p0 = g_pos_of[2 * t],  p1 = g_pos_of[2 * t + 1];
    float g0 = g_gate[2 * t],    g1 = g_gate[2 * t + 1];
    const uint2* y0 = reinterpret_cast<const uint2*>(g_yh + (size_t)p0 * D_IN);
    const uint2* y1 = reinterpret_cast<const uint2*>(g_yh + (size_t)p1 * D_IN);
    const float4* xr = reinterpret_cast<const float4*>(x + (size_t)t * D_IN);

    float4 xv = xr[tid];
    uint2 a0 = y0[tid];
    uint2 a1 = y1[tid];
    float2 f00 = __half22float2(*reinterpret_cast<__half2*>(&a0.x));
    float2 f01 = __half22float2(*reinterpret_cast<__half2*>(&a0.y));
    float2 f10 = __half22float2(*reinterpret_cast<__half2*>(&a1.x));
    float2 f11 = __half22float2(*reinterpret_cast<__half2*>(&a1.y));

    float v[4];
    v[0] = fmaf(g0, f00.x, fmaf(g1, f10.x, xv.x));
    v[1] = fmaf(g0, f00.y, fmaf(g1, f10.y, xv.y));
    v[2] = fmaf(g0, f01.x, fmaf(g1, f11.x, xv.z));
    v[3] = fmaf(g0, f01.y, fmaf(g1, f11.y, xv.w));

    float s = 0.f, sq = 0.f;
#pragma unroll
    for (int j = 0; j < 4; j++) { s += v[j]; sq = fmaf(v[j], v[j], sq); }
    *reinterpret_cast<float4*>(&vals[tid * 4]) = make_float4(v[0], v[1], v[2], v[3]);

#pragma unroll
    for (int off = 16; off; off >>= 1) {
        s  += __shfl_down_sync(0xffffffff, s,  off);
        sq += __shfl_down_sync(0xffffffff, sq, off);
    }
    if (lane == 0) { wsum[wid] = s; wsq[wid] = sq; }
    __syncthreads();
    if (wid == 0 && lane < 8) {
        float ss = wsum[lane], qq = wsq[lane];
#pragma unroll
        for (int off = 4; off; off >>= 1) {
            ss += __shfl_down_sync(0xff, ss, off);
            qq += __shfl_down_sync(0xff, qq, off);
        }
        if (lane == 0) {
            float mu = ss * (1.f / D_IN);
            float var = qq * (1.f / D_IN) - mu * mu;
            s_mu = mu;
            s_rs = rsqrtf(var + 1e-5f);
        }
    }
    __syncthreads();
    float mu = s_mu, rs = s_rs;

    const float4* g4 = reinterpret_cast<const float4*>(gamma);
    const float4* b4 = reinterpret_cast<const float4*>(beta);
    float4 gm = g4[tid], bt = b4[tid];
    float4 vv = *reinterpret_cast<float4*>(&vals[tid * 4]);
    float4 o;
    o.x = (vv.x - mu) * rs * gm.x + bt.x;
    o.y = (vv.y - mu) * rs * gm.y + bt.y;
    o.z = (vv.z - mu) * rs * gm.z + bt.z;
    o.w = (vv.w - mu) * rs * gm.w + bt.w;
    reinterpret_cast<float4*>(out + (size_t)t * D_IN)[tid] = o;
}

// ------------------------------ launch --------------------------------------
extern "C" void kernel_launch(void* const* d_in, const int* in_sizes, int n_in,
                              void* d_out, int out_size) {
    const float* x     = (const float*)d_in[0];
    const float* Wg    = (const float*)d_in[1];
    const float* W1    = (const float*)d_in[2];
    const float* b1    = (const float*)d_in[3];
    const float* W2    = (const float*)d_in[4];
    const float* b2    = (const float*)d_in[5];
    const float* gamma = (const float*)d_in[6];
    const float* beta  = (const float*)d_in[7];
    float* out = (float*)d_out;

    __half* hh;  cudaGetSymbolAddress((void**)&hh,  g_hh);
    __half* yh;  cudaGetSymbolAddress((void**)&yh,  g_yh);
    __half* xh;  cudaGetSymbolAddress((void**)&xh,  g_xh);
    __half* w1h; cudaGetSymbolAddress((void**)&w1h, g_w1h);
    __half* w2h; cudaGetSymbolAddress((void**)&w2h, g_w2h);

    // (1) weight conversion (independent)
    {
        int n8w = NEXP * D_IN * D_HID / 8;
        k_cvt_w<<<(2 * n8w + 255) / 256, 256>>>((const float4*)W1, (uint4*)w1h,
                                                (const float4*)W2, (uint4*)w2h, n8w);
    }
    // (2) gating + x->fp16 + row_token init
    k_gate<<<T_TOK / 8, 256>>>(x, Wg, xh);
    // (3) loss + scan + scatter
    k_scan_scatter_loss<<<1, 256>>>(out + (out_size - 1));

    // (4) GEMM1: h = fp16(relu(x_gathered @ W1[e] + b1[e]))   [rows x 2048]
    k_gemm_h<D_HID, D_IN, true, true>
        <<<dim3(MAX_TILES, D_HID / 64), 256, SMEM_BYTES>>>(xh, w1h, b1, hh);
    // (5) GEMM2: y = fp16(h @ W2[e] + b2[e])                  [rows x 1024]
    k_gemm_h<D_IN, D_HID, false, false>
        <<<dim3(MAX_TILES, D_IN / 64), 256, SMEM_BYTES>>>(hh, w2h, b2, yh);

    // (6) combine + residual + LayerNorm
    k_combine<<<T_TOK, 256>>>(x, gamma, beta, out);
}

// round 17
// speedup vs baseline: 1.2117x; 1.2117x over previous
#include <cuda_runtime.h>
#include <cuda_fp16.h>
#include <math.h>
#include <stdint.h>

// ---------------------------------------------------------------------------
// MoE FFN + residual + LayerNorm. fp16 mma.sync GEMMs, 128x128 tile,
// 512 threads / 16 warps (32x32 warp tile), 2 CTAs/SM.
// T=8192 tokens, D=1024, H=2048, E=8 experts, top-2.
// ---------------------------------------------------------------------------

constexpr int T_TOK = 8192;
constexpr int D_IN  = 1024;
constexpr int D_HID = 2048;
constexpr int NEXP  = 8;

constexpr int BM = 128;
constexpr int MAX_ROWS  = T_TOK * 2 + NEXP * BM; // 17408
constexpr int MAX_TILES = MAX_ROWS / BM;         // 136

// ------------------------- device scratch (static) -------------------------
__device__ __half g_hh [(size_t)MAX_ROWS * D_HID];       // GEMM1 out (fp16)
__device__ __half g_yh [(size_t)MAX_ROWS * D_IN];        // GEMM2 out (fp16)
__device__ __half g_xh [(size_t)T_TOK * D_IN];           // x  -> fp16 (in gate)
__device__ __half g_w1h[(size_t)NEXP * D_IN * D_HID];    // W1 -> fp16
__device__ __half g_w2h[(size_t)NEXP * D_HID * D_IN];    // W2 -> fp16
__device__ int   g_row_token[MAX_ROWS];
__device__ int   g_pos_of[T_TOK * 2];
__device__ int   g_sel[T_TOK * 2];
__device__ float g_gate[T_TOK * 2];
__device__ int   g_tile_expert[MAX_TILES];
__device__ int   g_n_tiles;

// --------------------------- PTX helpers -----------------------------------
__device__ __forceinline__ uint32_t smem_u32(const void* p) {
    uint32_t a;
    asm("{ .reg .u64 t; cvta.to.shared.u64 t, %1; cvt.u32.u64 %0, t; }"
        : "=r"(a) : "l"(p));
    return a;
}
__device__ __forceinline__ void mma_16816(float* c, const uint32_t* a,
                                          const uint32_t* b) {
    asm volatile(
        "mma.sync.aligned.m16n8k16.row.col.f32.f16.f16.f32 "
        "{%0,%1,%2,%3}, {%4,%5,%6,%7}, {%8,%9}, {%0,%1,%2,%3};"
        : "+f"(c[0]), "+f"(c[1]), "+f"(c[2]), "+f"(c[3])
        : "r"(a[0]), "r"(a[1]), "r"(a[2]), "r"(a[3]), "r"(b[0]), "r"(b[1]));
}
__device__ __forceinline__ void ldm_x4(uint32_t* r, uint32_t addr) {
    asm volatile("ldmatrix.sync.aligned.m8n8.x4.shared.b16 {%0,%1,%2,%3}, [%4];"
                 : "=r"(r[0]), "=r"(r[1]), "=r"(r[2]), "=r"(r[3]) : "r"(addr));
}
__device__ __forceinline__ void ldm_x4_t(uint32_t* r, uint32_t addr) {
    asm volatile("ldmatrix.sync.aligned.m8n8.x4.trans.shared.b16 {%0,%1,%2,%3}, [%4];"
                 : "=r"(r[0]), "=r"(r[1]), "=r"(r[2]), "=r"(r[3]) : "r"(addr));
}
__device__ __forceinline__ void cp16(uint32_t dst, const void* src, uint32_t sz) {
    asm volatile("cp.async.cg.shared.global [%0], [%1], 16, %2;"
                 :: "r"(dst), "l"(src), "r"(sz));
}
#define CP_COMMIT() asm volatile("cp.async.commit_group;" ::: "memory")
template <int N>
__device__ __forceinline__ void cp_wait() {
    asm volatile("cp.async.wait_group %0;" :: "n"(N) : "memory");
}

// ---------------- fused fp32 -> fp16 convert for W1 + W2 (proven) -----------
__global__ void k_cvt_w(const float4* __restrict__ w1, uint4* __restrict__ w1h,
                        const float4* __restrict__ w2, uint4* __restrict__ w2h,
                        int n8) {
    int i = blockIdx.x * blockDim.x + threadIdx.x;
    const float4* src; uint4* dst; int j;
    if (i < n8) { src = w1; dst = w1h; j = i; }
    else if (i < 2 * n8) { src = w2; dst = w2h; j = i - n8; }
    else return;
    float4 v0 = src[(size_t)j * 2], v1 = src[(size_t)j * 2 + 1];
    __half2 h0 = __floats2half2_rn(v0.x, v0.y);
    __half2 h1 = __floats2half2_rn(v0.z, v0.w);
    __half2 h2 = __floats2half2_rn(v1.x, v1.y);
    __half2 h3 = __floats2half2_rn(v1.z, v1.w);
    uint4 o;
    o.x = *reinterpret_cast<uint32_t*>(&h0);
    o.y = *reinterpret_cast<uint32_t*>(&h1);
    o.z = *reinterpret_cast<uint32_t*>(&h2);
    o.w = *reinterpret_cast<uint32_t*>(&h3);
    dst[j] = o;
}

// ----- gating (fp32, exact) + x->fp16 + row_token init (no atomics) ---------
__global__ void k_gate(const float* __restrict__ x, const float* __restrict__ Wg,
                       __half* __restrict__ xh) {
    int gid = blockIdx.x * blockDim.x + threadIdx.x;
    if (gid < MAX_ROWS) g_row_token[gid] = -1;

    int warp = threadIdx.x >> 5;
    int lane = threadIdx.x & 31;
    int t = blockIdx.x * 8 + warp;
    if (t >= T_TOK) return;
    const float* xr = x + (size_t)t * D_IN;
    __half* xhr = xh + (size_t)t * D_IN;
    const float4* wg4 = reinterpret_cast<const float4*>(Wg);

    float acc[8];
#pragma unroll
    for (int j = 0; j < 8; j++) acc[j] = 0.f;
    for (int i = lane; i < D_IN; i += 32) {
        float xv = xr[i];
        xhr[i] = __float2half_rn(xv);
        float4 a = wg4[i * 2];
        float4 b = wg4[i * 2 + 1];
        acc[0] += xv * a.x; acc[1] += xv * a.y; acc[2] += xv * a.z; acc[3] += xv * a.w;
        acc[4] += xv * b.x; acc[5] += xv * b.y; acc[6] += xv * b.z; acc[7] += xv * b.w;
    }
#pragma unroll
    for (int j = 0; j < 8; j++) {
#pragma unroll
        for (int off = 16; off; off >>= 1)
            acc[j] += __shfl_down_sync(0xffffffff, acc[j], off);
    }
    if (lane == 0) {
        int i0 = 0; float v0 = acc[0];
#pragma unroll
        for (int e = 1; e < 8; e++) if (acc[e] > v0) { v0 = acc[e]; i0 = e; }
        int i1 = -1; float v1 = -3.4e38f;
#pragma unroll
        for (int e = 0; e < 8; e++)
            if (e != i0 && acc[e] > v1) { v1 = acc[e]; i1 = e; }
        float e1 = expf(v1 - v0);
        float inv = 1.f / (1.f + e1);
        g_sel[2 * t] = i0;  g_sel[2 * t + 1] = i1;
        g_gate[2 * t] = inv; g_gate[2 * t + 1] = e1 * inv;
    }
}

// ------ loss reduction + scan (tid 0) + scatter (phase 2), single block -----
__global__ void k_scan_scatter_loss(float* __restrict__ loss_out) {
    __shared__ float simp[NEXP * 256];
    __shared__ float sld[NEXP * 256];
    __shared__ float rimp[NEXP], rld[NEXP];
    __shared__ int   s_cursor[NEXP];
    int tid = threadIdx.x;

    float imp[NEXP], ld[NEXP];
#pragma unroll
    for (int e = 0; e < NEXP; e++) { imp[e] = 0.f; ld[e] = 0.f; }
    for (int t = tid; t < T_TOK; t += 256) {
#pragma unroll
        for (int slot = 0; slot < 2; slot++) {
            int e = g_sel[2 * t + slot];
            imp[e] += g_gate[2 * t + slot];
            ld[e]  += 1.f;
        }
    }
#pragma unroll
    for (int e = 0; e < NEXP; e++) {
        simp[e * 256 + tid] = imp[e];
        sld[e * 256 + tid]  = ld[e];
    }
    __syncthreads();
    if (tid < NEXP) {
        float si = 0.f, sl = 0.f;
        for (int j = 0; j < 256; j++) { si += simp[tid * 256 + j]; sl += sld[tid * 256 + j]; }
        rimp[tid] = si; rld[tid] = sl;
    }
    __syncthreads();
    if (tid == 0) {
        int total_tiles = 0, pos = 0;
        for (int e = 0; e < NEXP; e++) {
            s_cursor[e] = pos;
            int cnt = (int)rld[e];
            int nt = (cnt + BM - 1) / BM;
            for (int j = 0; j < nt; j++) g_tile_expert[total_tiles + j] = e;
            total_tiles += nt;
            pos += nt * BM;
        }
        g_n_tiles = total_tiles;

        float mi = 0.f, ml = 0.f;
        for (int e = 0; e < NEXP; e++) { mi += rimp[e]; ml += rld[e]; }
        mi *= (1.f / NEXP); ml *= (1.f / NEXP);
        float vi = 0.f, vl = 0.f;
        for (int e = 0; e < NEXP; e++) {
            float d1 = rimp[e] - mi; vi += d1 * d1;
            float d2 = rld[e]  - ml; vl += d2 * d2;
        }
        vi *= (1.f / NEXP); vl *= (1.f / NEXP);
        *loss_out = vi / (mi * mi + 1e-10f) + vl / (ml * ml + 1e-10f);
    }
    __syncthreads();

    for (int t = tid; t < T_TOK; t += 256) {
#pragma unroll
        for (int slot = 0; slot < 2; slot++) {
            int e = g_sel[2 * t + slot];
            int p = atomicAdd(&s_cursor[e], 1);
            g_row_token[p] = t;
            g_pos_of[2 * t + slot] = p;
        }
    }
}

// ------------------- fp16 mma GEMM, 128x128 tile, 512 thr -------------------
// C[128 x 128] = A[128 x K] @ B[K x 128] (+bias, opt relu). BK=32, 2-stage,
// 16 warps (4x4) x (32x32) microtile, 2 CTAs/SM.
// As: [128][40] halfs (80B rows, ldmatrix conflict-free)
// Bs: [32][136] halfs (272B rows, ldmatrix.trans conflict-free)
constexpr int AS_HSTRIDE = 40;
constexpr int BS_HSTRIDE = 136;
constexpr int AS_BYTES = 128 * AS_HSTRIDE * 2;        // 10240
constexpr int BS_BYTES = 32 * BS_HSTRIDE * 2;         // 8704
constexpr int OFF_AS0 = 0;
constexpr int OFF_AS1 = AS_BYTES;
constexpr int OFF_BS0 = 2 * AS_BYTES;                 // 20480
constexpr int OFF_BS1 = 2 * AS_BYTES + BS_BYTES;      // 29184
constexpr int OFF_BIAS = 2 * AS_BYTES + 2 * BS_BYTES; // 37888
constexpr int SMEM_BYTES = OFF_BIAS + 512;            // 38400

template <int NTOT, int K, bool GATHER, bool RELU>
__global__ void __launch_bounds__(512, 2) k_gemm_h(const __half* __restrict__ A,
                                                   const __half* __restrict__ Bg,
                                                   const float* __restrict__ bias,
                                                   __half* __restrict__ C) {
    extern __shared__ char smem[];
    uint32_t sb = smem_u32(smem);
    int tile = blockIdx.x;
    if (tile >= g_n_tiles) return;
    int e    = g_tile_expert[tile];
    int row0 = tile * BM;
    int n0   = blockIdx.y * 128;
    int tid  = threadIdx.x;
    int lane = tid & 31, wid = tid >> 5;
    int g = lane >> 2, t = lane & 3;
    int m_off = (wid & 3) * 32;
    int n_off = (wid >> 2) * 32;

    float* sbias = (float*)(smem + OFF_BIAS);
    if (tid < 128) sbias[tid] = bias[(size_t)e * NTOT + n0 + tid];

    // ---- cp.async mapping: A 128 rows x 64B -> 4 thr/row, 1 cp16 each
    //                        B  32 rows x 256B -> 16 thr/row, 1 cp16 each
    int arow = tid >> 2, au = tid & 3;
    const __half* asrc; uint32_t avalid = 16u;
    if (GATHER) {
        int tok = g_row_token[row0 + arow];
        avalid = (tok >= 0) ? 16u : 0u;
        asrc = A + (size_t)(tok < 0 ? 0 : tok) * K + au * 8;
    } else {
        asrc = A + (size_t)(row0 + arow) * K + au * 8;
    }
    int brow = tid >> 4, bu = tid & 15;
    const __half* bsrc = Bg + (size_t)e * K * NTOT + (size_t)brow * NTOT + n0 + bu * 8;

    uint32_t a_dst0 = sb + OFF_AS0 + arow * (AS_HSTRIDE * 2) + au * 16;
    uint32_t a_dst1 = sb + OFF_AS1 + arow * (AS_HSTRIDE * 2) + au * 16;
    uint32_t b_dst0 = sb + OFF_BS0 + brow * (BS_HSTRIDE * 2) + bu * 16;
    uint32_t b_dst1 = sb + OFF_BS1 + brow * (BS_HSTRIDE * 2) + bu * 16;

    auto load_chunk = [&](int i, int s) {
        int k0 = i * 32;
        cp16(s ? a_dst1 : a_dst0, asrc + k0, avalid);
        cp16(s ? b_dst1 : b_dst0, bsrc + (size_t)k0 * NTOT, 16u);
        CP_COMMIT();
    };

    // ---- ldmatrix per-lane base offsets (proven formulas) ----
    uint32_t a_lm = (uint32_t)((m_off + (lane & 7) + ((lane >> 3) & 1) * 8) * (AS_HSTRIDE * 2)
                               + (lane >> 4) * 16);
    uint32_t b_lm = (uint32_t)(((lane & 7) + ((lane >> 3) & 1) * 8) * (BS_HSTRIDE * 2)
                               + (n_off + (lane >> 4) * 8) * 2);

    float acc[2][4][4];
#pragma unroll
    for (int mt = 0; mt < 2; mt++)
#pragma unroll
        for (int nt = 0; nt < 4; nt++)
#pragma unroll
            for (int q = 0; q < 4; q++) acc[mt][nt][q] = 0.f;

    load_chunk(0, 0);
    load_chunk(1, 1);

    constexpr int NK = K / 32;
    for (int i = 0; i < NK; i++) {
        int s = i & 1;
        if (i + 1 < NK) cp_wait<1>(); else cp_wait<0>();
        __syncthreads();
        uint32_t as_base = sb + (s ? OFF_AS1 : OFF_AS0) + a_lm;
        uint32_t bs_base = sb + (s ? OFF_BS1 : OFF_BS0) + b_lm;
#pragma unroll
        for (int ks = 0; ks < 2; ks++) {
            uint32_t a[2][4], b[4][2];
#pragma unroll
            for (int mt = 0; mt < 2; mt++)
                ldm_x4(a[mt], as_base + ks * 32 + mt * 16 * (AS_HSTRIDE * 2));
#pragma unroll
            for (int p = 0; p < 2; p++) {
                uint32_t r[4];
                ldm_x4_t(r, bs_base + ks * 16 * (BS_HSTRIDE * 2) + p * 32);
                b[2 * p][0] = r[0]; b[2 * p][1] = r[1];
                b[2 * p + 1][0] = r[2]; b[2 * p + 1][1] = r[3];
            }
#pragma unroll
            for (int mt = 0; mt < 2; mt++)
#pragma unroll
                for (int nt = 0; nt < 4; nt++)
                    mma_16816(acc[mt][nt], a[mt], b[nt]);
        }
        __syncthreads();
        if (i + 2 < NK) load_chunk(i + 2, s);
    }

    // ---- epilogue (fp16 out) ----
#pragma unroll
    for (int mt = 0; mt < 2; mt++) {
        int r0 = row0 + m_off + mt * 16 + g;
        __half* c0 = C + (size_t)r0 * NTOT + n0;
        __half* c1 = c0 + (size_t)8 * NTOT;
#pragma unroll
        for (int nt = 0; nt < 4; nt++) {
            int col = n_off + nt * 8 + t * 2;
            float v[4];
            v[0] = acc[mt][nt][0] + sbias[col];
            v[1] = acc[mt][nt][1] + sbias[col + 1];
            v[2] = acc[mt][nt][2] + sbias[col];
            v[3] = acc[mt][nt][3] + sbias[col + 1];
            if (RELU) {
#pragma unroll
                for (int q = 0; q < 4; q++) v[q] = fmaxf(v[q], 0.f);
            }
            *reinterpret_cast<__half2*>(c0 + col) = __floats2half2_rn(v[0], v[1]);
            *reinterpret_cast<__half2*>(c1 + col) = __floats2half2_rn(v[2], v[3]);
        }
    }
}

// ----------- combine + residual + LayerNorm (vectorized, 1-pass stats) ------
__global__ void __launch_bounds__(256) k_combine(const float* __restrict__ x,
                                                 const float* __restrict__ gamma,
                                                 const float* __restrict__ beta,
                                                 float* __restrict__ out) {
    __shared__ float vals[D_IN];
    __shared__ float wsum[8], wsq[8];
    __shared__ float s_mu, s_rs;
    int t = blockIdx.x;
    int tid = threadIdx.x;
    int lane = tid & 31, wid = tid >> 5;

    int   p0 = g_pos_of[2 * t],  p1 = g_pos_of[2 * t + 1];
    float g0 = g_gate[2 * t],    g1 = g_gate[2 * t + 1];
    const uint2* y0 = reinterpret_cast<const uint2*>(g_yh + (size_t)p0 * D_IN);
    const uint2* y1 = reinterpret_cast<const uint2*>(g_yh + (size_t)p1 * D_IN);
    const float4* xr = reinterpret_cast<const float4*>(x + (size_t)t * D_IN);

    float4 xv = xr[tid];
    uint2 a0 = y0[tid];
    uint2 a1 = y1[tid];
    float2 f00 = __half22float2(*reinterpret_cast<__half2*>(&a0.x));
    float2 f01 = __half22float2(*reinterpret_cast<__half2*>(&a0.y));
    float2 f10 = __half22float2(*reinterpret_cast<__half2*>(&a1.x));
    float2 f11 = __half22float2(*reinterpret_cast<__half2*>(&a1.y));

    float v[4];
    v[0] = fmaf(g0, f00.x, fmaf(g1, f10.x, xv.x));
    v[1] = fmaf(g0, f00.y, fmaf(g1, f10.y, xv.y));
    v[2] = fmaf(g0, f01.x, fmaf(g1, f11.x, xv.z));
    v[3] = fmaf(g0, f01.y, fmaf(g1, f11.y, xv.w));

    float s = 0.f, sq = 0.f;
#pragma unroll
    for (int j = 0; j < 4; j++) { s += v[j]; sq = fmaf(v[j], v[j], sq); }
    *reinterpret_cast<float4*>(&vals[tid * 4]) = make_float4(v[0], v[1], v[2], v[3]);

#pragma unroll
    for (int off = 16; off; off >>= 1) {
        s  += __shfl_down_sync(0xffffffff, s,  off);
        sq += __shfl_down_sync(0xffffffff, sq, off);
    }
    if (lane == 0) { wsum[wid] = s; wsq[wid] = sq; }
    __syncthreads();
    if (wid == 0 && lane < 8) {
        float ss = wsum[lane], qq = wsq[lane];
#pragma unroll
        for (int off = 4; off; off >>= 1) {
            ss += __shfl_down_sync(0xff, ss, off);
            qq += __shfl_down_sync(0xff, qq, off);
        }
        if (lane == 0) {
            float mu = ss * (1.f / D_IN);
            float var = qq * (1.f / D_IN) - mu * mu;
            s_mu = mu;
            s_rs = rsqrtf(var + 1e-5f);
        }
    }
    __syncthreads();
    float mu = s_mu, rs = s_rs;

    const float4* g4 = reinterpret_cast<const float4*>(gamma);
    const float4* b4 = reinterpret_cast<const float4*>(beta);
    float4 gm = g4[tid], bt = b4[tid];
    float4 vv = *reinterpret_cast<float4*>(&vals[tid * 4]);
    float4 o;
    o.x = (vv.x - mu) * rs * gm.x + bt.x;
    o.y = (vv.y - mu) * rs * gm.y + bt.y;
    o.z = (vv.z - mu) * rs * gm.z + bt.z;
    o.w = (vv.w - mu) * rs * gm.w + bt.w;
    reinterpret_cast<float4*>(out + (size_t)t * D_IN)[tid] = o;
}

// ------------------------------ launch --------------------------------------
extern "C" void kernel_launch(void* const* d_in, const int* in_sizes, int n_in,
                              void* d_out, int out_size) {
    const float* x     = (const float*)d_in[0];
    const float* Wg    = (const float*)d_in[1];
    const float* W1    = (const float*)d_in[2];
    const float* b1    = (const float*)d_in[3];
    const float* W2    = (const float*)d_in[4];
    const float* b2    = (const float*)d_in[5];
    const float* gamma = (const float*)d_in[6];
    const float* beta  = (const float*)d_in[7];
    float* out = (float*)d_out;

    __half* hh;  cudaGetSymbolAddress((void**)&hh,  g_hh);
    __half* yh;  cudaGetSymbolAddress((void**)&yh,  g_yh);
    __half* xh;  cudaGetSymbolAddress((void**)&xh,  g_xh);
    __half* w1h; cudaGetSymbolAddress((void**)&w1h, g_w1h);
    __half* w2h; cudaGetSymbolAddress((void**)&w2h, g_w2h);

    // (1) weight conversion (independent)
    {
        int n8w = NEXP * D_IN * D_HID / 8;
        k_cvt_w<<<(2 * n8w + 255) / 256, 256>>>((const float4*)W1, (uint4*)w1h,
                                                (const float4*)W2, (uint4*)w2h, n8w);
    }
    // (2) gating + x->fp16 + row_token init
    k_gate<<<T_TOK / 8, 256>>>(x, Wg, xh);
    // (3) loss + scan + scatter
    k_scan_scatter_loss<<<1, 256>>>(out + (out_size - 1));

    // (4) GEMM1: h = fp16(relu(x_gathered @ W1[e] + b1[e]))   [rows x 2048]
    k_gemm_h<D_HID, D_IN, true, true>
        <<<dim3(MAX_TILES, D_HID / 128), 512, SMEM_BYTES>>>(xh, w1h, b1, hh);
    // (5) GEMM2: y = fp16(h @ W2[e] + b2[e])                  [rows x 1024]
    k_gemm_h<D_IN, D_HID, false, false>
        <<<dim3(MAX_TILES, D_IN / 128), 512, SMEM_BYTES>>>(hh, w2h, b2, yh);

    // (6) combine + residual + LayerNorm
    k_combine<<<T_TOK, 256>>>(x, gamma, beta, out);
}